// round 1
// baseline (speedup 1.0000x reference)
#include <cuda_runtime.h>

#define D   64
#define KC  1024
#define NMAX 131072
#define MARGIN 4e-5f

// ---------------- device scratch (static — no allocation) ----------------
__device__ float  g_eT[D * KC];        // transposed codebook for rescore (coalesced)
__device__ float  g_ee[KC];            // ||e||^2 per code, reference-order accumulation
__device__ int    g_codes[NMAX];       // argmin result (int staging)
__device__ int    g_ambig_rows[NMAX];  // rows needing exact rescore
__device__ int    g_num_ambig;
__device__ double g_loss_sum;

// ---------------- helpers ----------------
__device__ __forceinline__ void fma2(unsigned long long &acc,
                                     unsigned long long a, unsigned long long b) {
    asm("fma.rn.f32x2 %0, %1, %2, %0;" : "+l"(acc) : "l"(a), "l"(b));
}
__device__ __forceinline__ float2 unpack2(unsigned long long u) {
    float2 f; asm("mov.b64 {%0, %1}, %2;" : "=f"(f.x), "=f"(f.y) : "l"(u)); return f;
}

// ---------------- kernel 0: init (ee, e^T, counters) ----------------
__global__ void vq_init_kernel(const float* __restrict__ cb) {
    int j = blockIdx.x * blockDim.x + threadIdx.x;
    if (j == 0) { g_loss_sum = 0.0; g_num_ambig = 0; }
    if (j < KC) {
        const float* er = cb + (size_t)j * D;
        float ee = 0.f;
        #pragma unroll
        for (int k = 0; k < D; ++k) {
            float v = er[k];
            ee = __fadd_rn(ee, __fmul_rn(v, v));   // mul-then-add, sequential (XLA reduce guess)
            g_eT[k * KC + j] = v;
        }
        g_ee[j] = ee;
    }
}

// ---------------- kernel 1: fast argmin screen (f32x2 FMAs) ----------------
__global__ __launch_bounds__(256, 2) void vq_argmin_kernel(
    const float* __restrict__ x, const float* __restrict__ cb, int nrows)
{
    __shared__ __align__(16) float s_e[128 * D];
    __shared__ float s_ee[128];
    int tid = threadIdx.x;
    int row = blockIdx.x * 256 + tid;   // grid sized so row < nrows always

    // whole input row in registers, packed as f32 pairs
    unsigned long long xp[32];
    const ulonglong2* xr = (const ulonglong2*)(x + (size_t)row * D);
    #pragma unroll
    for (int i = 0; i < 16; ++i) { ulonglong2 v = xr[i]; xp[2*i] = v.x; xp[2*i+1] = v.y; }

    float m1 = 3.4e38f, m2 = 3.4e38f;
    int i1 = 0;

    #pragma unroll 1
    for (int c0 = 0; c0 < KC; c0 += 128) {
        __syncthreads();
        const float4* src = (const float4*)(cb + (size_t)c0 * D);
        #pragma unroll 1
        for (int i = tid; i < 128 * D / 4; i += 256) ((float4*)s_e)[i] = src[i];
        if (tid < 128) s_ee[tid] = g_ee[c0 + tid];
        __syncthreads();

        #pragma unroll 1
        for (int j = 0; j < 128; ++j) {
            const ulonglong2* ev = (const ulonglong2*)(s_e + j * D);
            unsigned long long a0 = 0ull, a1 = 0ull;
            #pragma unroll
            for (int i = 0; i < 16; ++i) {
                ulonglong2 e2 = ev[i];           // LDS.128, uniform addr -> broadcast
                fma2(a0, xp[2*i],   e2.x);
                fma2(a1, xp[2*i+1], e2.y);
            }
            float2 f0 = unpack2(a0), f1 = unpack2(a1);
            float dot = __fadd_rn(__fadd_rn(f0.x, f0.y), __fadd_rn(f1.x, f1.y));
            float sc  = __fmaf_rn(-2.f, dot, s_ee[j]);   // screen score (xx term is row-constant)
            int gj = c0 + j;
            if (sc < m1)      { m2 = m1; m1 = sc; i1 = gj; }  // strict <: first-index wins
            else if (sc < m2) { m2 = sc; }
        }
    }
    g_codes[row] = i1;
    if (m2 - m1 < MARGIN) {                 // winner not certain under ref's fp32 rounding
        int s = atomicAdd(&g_num_ambig, 1);
        g_ambig_rows[s] = row;
    }
}

// ---------------- kernel 2: exact reference-numerics rescore ----------------
__global__ __launch_bounds__(256) void vq_rescore_kernel(const float* __restrict__ x)
{
    int gw     = (blockIdx.x * blockDim.x + threadIdx.x) >> 5;
    int lane   = threadIdx.x & 31;
    int nwarps = (gridDim.x * blockDim.x) >> 5;
    int na = g_num_ambig;
    for (int s = gw; s < na; s += nwarps) {
        int row = g_ambig_rows[s];
        const float* xr = x + (size_t)row * D;
        float xv[D];
        #pragma unroll
        for (int k = 0; k < D; ++k) xv[k] = xr[k];

        // xx = sum(x*x): mul then add, strictly sequential ascending
        float xx = 0.f;
        #pragma unroll
        for (int k = 0; k < D; ++k) xx = __fadd_rn(xx, __fmul_rn(xv[k], xv[k]));

        float bestd = 3.4e38f; int besti = KC;
        #pragma unroll 1
        for (int it = 0; it < KC / 32; ++it) {
            int j = it * 32 + lane;
            // A = dot(x, e_j): sequential fused-fma ascending (Eigen gebp order)
            float acc = 0.f;
            #pragma unroll
            for (int k = 0; k < D; ++k) acc = __fmaf_rn(xv[k], g_eT[k * KC + j], acc);
            float t  = __fadd_rn(xx, __fmul_rn(-2.f, acc));  // 2*A exact; one fp32 round
            float dd = __fadd_rn(t, g_ee[j]);                // second fp32 round
            if (dd < bestd) { bestd = dd; besti = j; }       // per-lane j ascending: first wins
        }
        #pragma unroll
        for (int off = 16; off; off >>= 1) {                 // lexicographic (d, idx) min
            float od = __shfl_down_sync(0xffffffffu, bestd, off);
            int   oi = __shfl_down_sync(0xffffffffu, besti, off);
            if (od < bestd || (od == bestd && oi < besti)) { bestd = od; besti = oi; }
        }
        if (lane == 0) g_codes[row] = besti;
    }
}

// ---------------- kernel 3: straight_through + loss accumulation ----------------
__global__ __launch_bounds__(256) void vq_st_loss_kernel(
    const float* __restrict__ x, const float* __restrict__ cb,
    float* __restrict__ out, int nrows)
{
    __shared__ double sd[256];
    int i4 = blockIdx.x * 256 + threadIdx.x;   // float4 index
    double ls = 0.0;
    if (i4 < nrows * 16) {
        int row = i4 >> 4, c = i4 & 15;
        int code = g_codes[row];
        float4 xv = ((const float4*)x)[i4];
        float4 qv = ((const float4*)cb)[(size_t)code * 16 + c];
        float4 st;
        st.x = __fadd_rn(xv.x, __fsub_rn(qv.x, xv.x));
        st.y = __fadd_rn(xv.y, __fsub_rn(qv.y, xv.y));
        st.z = __fadd_rn(xv.z, __fsub_rn(qv.z, xv.z));
        st.w = __fadd_rn(xv.w, __fsub_rn(qv.w, xv.w));
        ((float4*)out)[i4] = st;
        float dx = __fsub_rn(xv.x, qv.x), dy = __fsub_rn(xv.y, qv.y);
        float dz = __fsub_rn(xv.z, qv.z), dw = __fsub_rn(xv.w, qv.w);
        ls = (double)__fmul_rn(dx, dx) + (double)__fmul_rn(dy, dy)
           + (double)__fmul_rn(dz, dz) + (double)__fmul_rn(dw, dw);
    }
    sd[threadIdx.x] = ls;
    __syncthreads();
    for (int off = 128; off; off >>= 1) {
        if (threadIdx.x < off) sd[threadIdx.x] += sd[threadIdx.x + off];
        __syncthreads();
    }
    if (threadIdx.x == 0) atomicAdd(&g_loss_sum, sd[0]);
}

// ---------------- kernel 4: codes (as float) + loss scalar ----------------
__global__ void vq_codes_loss_kernel(float* __restrict__ out, int nrows, long long out_size)
{
    long long r    = (long long)blockIdx.x * blockDim.x + threadIdx.x;
    long long coff = (long long)nrows * D;
    if (r < nrows && coff + r < out_size) out[coff + r] = (float)g_codes[r];
    if (r == 0 && coff + nrows < out_size) {
        double mean = g_loss_sum / (double)((long long)nrows * D);
        float  mf   = (float)mean;                         // commitment == codebook_loss
        out[coff + nrows] = __fadd_rn(mf, __fmul_rn(0.25f, mf));
    }
}

// ---------------- launch ----------------
extern "C" void kernel_launch(void* const* d_in, const int* in_sizes, int n_in,
                              void* d_out, int out_size)
{
    const float* x  = (const float*)d_in[0];
    const float* cb = (const float*)d_in[1];
    int nx = in_sizes[0], nc = in_sizes[1];
    if (nx < nc) {                 // codebook is the smaller tensor (1024*64)
        const float* t = x; x = cb; cb = t;
        int ti = nx; nx = nc; nc = ti;
    }
    int nrows = nx / D;            // 131072
    float* out = (float*)d_out;

    vq_init_kernel<<<4, 256>>>(cb);
    vq_argmin_kernel<<<nrows / 256, 256>>>(x, cb, nrows);
    vq_rescore_kernel<<<128, 256>>>(x);
    vq_st_loss_kernel<<<(nrows * 16 + 255) / 256, 256>>>(x, cb, out, nrows);
    vq_codes_loss_kernel<<<(nrows + 255) / 256, 256>>>(out, nrows, (long long)out_size);
}

// round 3
// speedup vs baseline: 3.0815x; 3.0815x over previous
#include <cuda_runtime.h>
#include <cstdint>

#define EDIM  64
#define KC    1024
#define NMAX  131072
#define MARGIN 3e-4f

// ---------------- device scratch (static — no allocation) ----------------
__device__ __align__(16) float g_BnegT[EDIM * KC];  // tf32 bits of -2*cb, [k][j] layout
__device__ float  g_ee[KC];                          // ||e||^2, reference-order accumulation
__device__ int    g_codes[NMAX];
__device__ int    g_ambig_rows[NMAX];
__device__ unsigned long long g_amb_key[NMAX];       // packed (d_bits<<32)|idx, min-merged
__device__ int    g_num_ambig;
__device__ double g_loss_sum;

// ---------------- helpers ----------------
__device__ __forceinline__ uint32_t smem_to_u32(const void* p) {
    uint32_t a;
    asm("{ .reg .u64 t; cvta.to.shared.u64 t, %1; cvt.u32.u64 %0, t; }" : "=r"(a) : "l"(p));
    return a;
}
__device__ __forceinline__ uint32_t cvt_tf32(float f) {
    uint32_t u;
    asm("cvt.rna.tf32.f32 %0, %1;" : "=r"(u) : "f"(f));
    return u;
}
__device__ __forceinline__ void mma_tf32(float c[4], uint32_t a0, uint32_t a1,
                                         uint32_t a2, uint32_t a3,
                                         uint32_t b0, uint32_t b1) {
    asm volatile("mma.sync.aligned.m16n8k8.row.col.f32.tf32.tf32.f32 "
                 "{%0,%1,%2,%3}, {%4,%5,%6,%7}, {%8,%9}, {%0,%1,%2,%3};"
                 : "+f"(c[0]), "+f"(c[1]), "+f"(c[2]), "+f"(c[3])
                 : "r"(a0), "r"(a1), "r"(a2), "r"(a3), "r"(b0), "r"(b1));
}
#define CP_COMMIT() asm volatile("cp.async.commit_group;" ::: "memory")
#define CP_WAIT0()  asm volatile("cp.async.wait_group 0;" ::: "memory")

// ---------------- kernel 0: init ----------------
__global__ void vq_init_kernel(const float* __restrict__ cb) {
    int j = blockIdx.x * blockDim.x + threadIdx.x;
    if (j == 0) { g_loss_sum = 0.0; g_num_ambig = 0; }
    if (j < KC) {
        const float* er = cb + (size_t)j * EDIM;
        float ee = 0.f;
        #pragma unroll
        for (int k = 0; k < EDIM; ++k) {
            float v = er[k];
            ee = __fadd_rn(ee, __fmul_rn(v, v));          // reference-exact order
            g_BnegT[k * KC + j] = __uint_as_float(cvt_tf32(__fmul_rn(-2.f, v)));
        }
        g_ee[j] = ee;
    }
}

// ---------------- kernel 1: tf32 mma.sync screen + fused argmin ----------------
// smem: A[128][68] f32 @0 (34816B) | B[2][64][136] f32 @34816 (2x34816B)
#define SMEM_A_STRIDE 68
#define SMEM_B_OFF    34816
#define SMEM_B_STRIDE 136
#define SMEM_SZ       104448

__device__ __forceinline__ void cp_chunk(char* smdst, int c, int tid) {
    uint32_t d0 = smem_to_u32(smdst);
    #pragma unroll
    for (int it = 0; it < 8; ++it) {
        int i = tid + it * 256;
        int k = i >> 5, j4 = i & 31;
        uint32_t d = d0 + k * (SMEM_B_STRIDE * 4) + j4 * 16;
        const float* s = g_BnegT + k * KC + c * 128 + j4 * 4;
        asm volatile("cp.async.cg.shared.global [%0], [%1], 16;" :: "r"(d), "l"(s));
    }
}

__global__ __launch_bounds__(256, 2) void vq_screen_mma(const float* __restrict__ x, int nrows) {
    extern __shared__ __align__(16) char sm[];
    int tid = threadIdx.x, wid = tid >> 5, lane = tid & 31;
    int g = lane >> 2, tig = lane & 3;
    int m0 = blockIdx.x * 128;

    // ---- stage A tile (tf32-converted, padded stride 68) ----
    const float4* x4 = (const float4*)(x + (size_t)m0 * EDIM);
    #pragma unroll
    for (int it = 0; it < 8; ++it) {
        int i = tid + it * 256;
        int row = i >> 4, c4 = i & 15;
        uint4 u = make_uint4(0u, 0u, 0u, 0u);
        if (m0 + row < nrows) {
            float4 v = x4[i];
            u.x = cvt_tf32(v.x); u.y = cvt_tf32(v.y);
            u.z = cvt_tf32(v.z); u.w = cvt_tf32(v.w);
        }
        *(uint4*)(sm + row * (SMEM_A_STRIDE * 4) + c4 * 16) = u;
    }
    cp_chunk(sm + SMEM_B_OFF, 0, tid);
    CP_COMMIT();
    CP_WAIT0();
    __syncthreads();

    // ---- load A fragments into registers (one m16 tile per warp) ----
    const uint32_t* pa = (const uint32_t*)sm + (wid * 16 + g) * SMEM_A_STRIDE + tig;
    uint32_t A0[8], A1[8], A2[8], A3[8];
    #pragma unroll
    for (int s = 0; s < 8; ++s) {
        A0[s] = pa[s * 8];
        A2[s] = pa[s * 8 + 4];
        A1[s] = pa[8 * SMEM_A_STRIDE + s * 8];
        A3[s] = pa[8 * SMEM_A_STRIDE + s * 8 + 4];
    }

    float m1s[2] = {3.4e38f, 3.4e38f}, m2s[2] = {3.4e38f, 3.4e38f};
    int   i1s[2] = {0, 0};

    #pragma unroll 1
    for (int c = 0; c < 8; ++c) {
        int buf = c & 1;
        if (c + 1 < 8) {
            cp_chunk(sm + SMEM_B_OFF + (buf ^ 1) * 34816, c + 1, tid);
            CP_COMMIT();
        }
        const uint32_t* pb = (const uint32_t*)(sm + SMEM_B_OFF + buf * 34816)
                             + tig * SMEM_B_STRIDE + g;
        int cbase = c * 128;

        #pragma unroll 1
        for (int tp = 0; tp < 8; ++tp) {
            int t0 = tp * 2;
            float c0[4] = {0.f, 0.f, 0.f, 0.f};
            float c1[4] = {0.f, 0.f, 0.f, 0.f};
            #pragma unroll
            for (int s = 0; s < 8; ++s) {
                const uint32_t* pbs = pb + s * (8 * SMEM_B_STRIDE) + t0 * 8;
                uint32_t b00 = pbs[0];
                uint32_t b01 = pbs[4 * SMEM_B_STRIDE];
                uint32_t b10 = pbs[8];
                uint32_t b11 = pbs[4 * SMEM_B_STRIDE + 8];
                mma_tf32(c0, A0[s], A1[s], A2[s], A3[s], b00, b01);
                mma_tf32(c1, A0[s], A1[s], A2[s], A3[s], b10, b11);
            }
            int jb0 = cbase + t0 * 8 + 2 * tig;
            int jb1 = jb0 + 8;
            // slot 0 = row g, slot 1 = row g+8; ascending j, strict < => first index wins
            #pragma unroll
            for (int slot = 0; slot < 2; ++slot) {
                float v0 = c0[slot * 2], v1 = c0[slot * 2 + 1];
                float w0 = c1[slot * 2], w1 = c1[slot * 2 + 1];
                float m1 = m1s[slot], m2 = m2s[slot]; int i1 = i1s[slot];
                if (v0 < m1) { m2 = m1; m1 = v0; i1 = jb0; }     else if (v0 < m2) m2 = v0;
                if (v1 < m1) { m2 = m1; m1 = v1; i1 = jb0 + 1; } else if (v1 < m2) m2 = v1;
                if (w0 < m1) { m2 = m1; m1 = w0; i1 = jb1; }     else if (w0 < m2) m2 = w0;
                if (w1 < m1) { m2 = m1; m1 = w1; i1 = jb1 + 1; } else if (w1 < m2) m2 = w1;
                m1s[slot] = m1; m2s[slot] = m2; i1s[slot] = i1;
            }
        }
        if (c + 1 < 8) CP_WAIT0();
        __syncthreads();
    }

    // ---- merge across the 4 lanes of each row-quad (lexicographic (val, idx)) ----
    #pragma unroll
    for (int slot = 0; slot < 2; ++slot) {
        float a1 = m1s[slot], a2 = m2s[slot]; int ai = i1s[slot];
        #pragma unroll
        for (int off = 1; off <= 2; off <<= 1) {
            float o1 = __shfl_xor_sync(0xffffffffu, a1, off);
            int   oi = __shfl_xor_sync(0xffffffffu, ai, off);
            float o2 = __shfl_xor_sync(0xffffffffu, a2, off);
            if (o1 < a1 || (o1 == a1 && oi < ai)) {
                a2 = fminf(o2, a1); a1 = o1; ai = oi;
            } else {
                a2 = fminf(a2, o1);
            }
        }
        if (tig == 0) {
            int row = m0 + wid * 16 + g + slot * 8;
            if (row < nrows) {
                g_codes[row] = ai;
                if (a2 - a1 < MARGIN) {
                    int s = atomicAdd(&g_num_ambig, 1);
                    g_ambig_rows[s] = row;
                    g_amb_key[s] = ~0ull;
                }
            }
        }
    }
}

// ---------------- kernel 2: exact reference-numerics rescore (tiled, segmented) ----------------
__global__ __launch_bounds__(256) void vq_rescore_seg(const float* __restrict__ x,
                                                      const float* __restrict__ cb) {
    __shared__ float s_e[128 * EDIM];
    int na = g_num_ambig;
    int nwork = ((na + 255) >> 8) * 8;
    #pragma unroll 1
    for (int w = blockIdx.x; w < nwork; w += gridDim.x) {
        int seg = w & 7, base = (w >> 3) << 8;
        __syncthreads();
        const float4* g4 = (const float4*)(cb + (size_t)seg * 128 * EDIM);
        for (int i = threadIdx.x; i < 2048; i += 256) ((float4*)s_e)[i] = g4[i];
        __syncthreads();
        int s = base + threadIdx.x;
        if (s < na) {
            int row = g_ambig_rows[s];
            const float* xr = x + (size_t)row * EDIM;
            float xv[EDIM];
            #pragma unroll
            for (int k = 0; k < EDIM; ++k) xv[k] = xr[k];
            float xx = 0.f;                                  // reference-exact
            #pragma unroll
            for (int k = 0; k < EDIM; ++k) xx = __fadd_rn(xx, __fmul_rn(xv[k], xv[k]));
            float bd = 3.4e38f; int bi = 0x7fffffff;
            #pragma unroll 1
            for (int jj = 0; jj < 128; jj += 2) {            // 2-way ILP on serial chains
                const float* e0 = s_e + jj * EDIM;
                const float* e1 = e0 + EDIM;
                float a0 = 0.f, a1 = 0.f;
                #pragma unroll
                for (int k = 0; k < EDIM; ++k) {
                    a0 = __fmaf_rn(xv[k], e0[k], a0);
                    a1 = __fmaf_rn(xv[k], e1[k], a1);
                }
                int j0 = seg * 128 + jj;
                float d0 = __fadd_rn(__fadd_rn(xx, __fmul_rn(-2.f, a0)), g_ee[j0]);
                float d1 = __fadd_rn(__fadd_rn(xx, __fmul_rn(-2.f, a1)), g_ee[j0 + 1]);
                if (d0 < bd) { bd = d0; bi = j0; }
                if (d1 < bd) { bd = d1; bi = j0 + 1; }
            }
            unsigned long long key =
                ((unsigned long long)__float_as_uint(bd) << 32) | (unsigned)bi;
            atomicMin(&g_amb_key[s], key);                   // d>0: bit order == numeric order
        }
    }
}

__global__ void vq_rescore_fin() {
    int na = g_num_ambig;
    for (int s = blockIdx.x * blockDim.x + threadIdx.x; s < na; s += gridDim.x * blockDim.x)
        g_codes[g_ambig_rows[s]] = (int)(unsigned)(g_amb_key[s] & 0xffffffffull);
}

// ---------------- kernel 3: straight_through + loss (4 independent chains/thread) ----------------
__global__ __launch_bounds__(256) void vq_st_loss_kernel(
    const float* __restrict__ x, const float* __restrict__ cb,
    float* __restrict__ out, int nrows)
{
    int q = nrows * 4;                       // quarter of the float4 count
    int idx = blockIdx.x * 256 + threadIdx.x;
    double ls = 0.0;
    if (idx < q) {
        int    i4[4]; int code[4];
        float4 xv[4], qv[4];
        #pragma unroll
        for (int t = 0; t < 4; ++t) { i4[t] = idx + t * q; code[t] = g_codes[i4[t] >> 4]; }
        #pragma unroll
        for (int t = 0; t < 4; ++t) {
            xv[t] = ((const float4*)x)[i4[t]];
            qv[t] = ((const float4*)cb)[(size_t)code[t] * 16 + (i4[t] & 15)];
        }
        #pragma unroll
        for (int t = 0; t < 4; ++t) {
            float4 st;
            st.x = __fadd_rn(xv[t].x, __fsub_rn(qv[t].x, xv[t].x));
            st.y = __fadd_rn(xv[t].y, __fsub_rn(qv[t].y, xv[t].y));
            st.z = __fadd_rn(xv[t].z, __fsub_rn(qv[t].z, xv[t].z));
            st.w = __fadd_rn(xv[t].w, __fsub_rn(qv[t].w, xv[t].w));
            ((float4*)out)[i4[t]] = st;
            float dx = __fsub_rn(xv[t].x, qv[t].x), dy = __fsub_rn(xv[t].y, qv[t].y);
            float dz = __fsub_rn(xv[t].z, qv[t].z), dw = __fsub_rn(xv[t].w, qv[t].w);
            ls += (double)__fmul_rn(dx, dx) + (double)__fmul_rn(dy, dy)
                + (double)__fmul_rn(dz, dz) + (double)__fmul_rn(dw, dw);
        }
    }
    #pragma unroll
    for (int off = 16; off; off >>= 1)
        ls += __shfl_down_sync(0xffffffffu, ls, off);
    if ((threadIdx.x & 31) == 0) atomicAdd(&g_loss_sum, ls);
}

// ---------------- kernel 4: codes (as float) + loss scalar ----------------
__global__ void vq_codes_loss_kernel(float* __restrict__ out, int nrows, long long out_size)
{
    long long r    = (long long)blockIdx.x * blockDim.x + threadIdx.x;
    long long coff = (long long)nrows * EDIM;
    if (r < nrows && coff + r < out_size) out[coff + r] = (float)g_codes[r];
    if (r == 0 && coff + nrows < out_size) {
        double mean = g_loss_sum / (double)((long long)nrows * EDIM);
        float  mf   = (float)mean;
        out[coff + nrows] = __fadd_rn(mf, __fmul_rn(0.25f, mf));
    }
}

// ---------------- launch ----------------
extern "C" void kernel_launch(void* const* d_in, const int* in_sizes, int n_in,
                              void* d_out, int out_size)
{
    const float* x  = (const float*)d_in[0];
    const float* cb = (const float*)d_in[1];
    int nx = in_sizes[0], nc = in_sizes[1];
    if (nx < nc) {
        const float* t = x; x = cb; cb = t;
        int ti = nx; nx = nc; nc = ti;
    }
    int nrows = nx / EDIM;
    float* out = (float*)d_out;

    static int s_attr_done = 0;
    if (!s_attr_done) {
        cudaFuncSetAttribute(vq_screen_mma, cudaFuncAttributeMaxDynamicSharedMemorySize, SMEM_SZ);
        s_attr_done = 1;
    }

    vq_init_kernel<<<4, 256>>>(cb);
    vq_screen_mma<<<(nrows + 127) / 128, 256, SMEM_SZ>>>(x, nrows);
    vq_rescore_seg<<<296, 256>>>(x, cb);
    vq_rescore_fin<<<64, 256>>>();
    int q = nrows * 4;
    vq_st_loss_kernel<<<(q + 255) / 256, 256>>>(x, cb, out, nrows);
    vq_codes_loss_kernel<<<(nrows + 255) / 256, 256>>>(out, nrows, (long long)out_size);
}

// round 4
// speedup vs baseline: 3.0834x; 1.0006x over previous
#include <cuda_runtime.h>
#include <cstdint>

#define EDIM  64
#define KC    1024
#define NMAX  131072
#define MARGIN 3e-4f

// ---------------- device scratch (static — no allocation) ----------------
__device__ __align__(16) float g_BnegT[EDIM * KC];  // tf32 bits of -2*cb, [k][j] layout
__device__ float  g_ee[KC];                          // ||e||^2, reference-order accumulation
__device__ int    g_codes[NMAX];
__device__ int    g_ambig_rows[NMAX];
__device__ unsigned long long g_amb_key[NMAX];       // packed (d_bits<<32)|idx, min-merged
__device__ int    g_num_ambig;
__device__ double g_loss_sum;

// ---------------- helpers ----------------
__device__ __forceinline__ uint32_t smem_to_u32(const void* p) {
    uint32_t a;
    asm("{ .reg .u64 t; cvta.to.shared.u64 t, %1; cvt.u32.u64 %0, t; }" : "=r"(a) : "l"(p));
    return a;
}
__device__ __forceinline__ uint32_t cvt_tf32(float f) {
    uint32_t u;
    asm("cvt.rna.tf32.f32 %0, %1;" : "=r"(u) : "f"(f));
    return u;
}
__device__ __forceinline__ void mma_tf32(float c[4], uint32_t a0, uint32_t a1,
                                         uint32_t a2, uint32_t a3,
                                         uint32_t b0, uint32_t b1) {
    asm volatile("mma.sync.aligned.m16n8k8.row.col.f32.tf32.tf32.f32 "
                 "{%0,%1,%2,%3}, {%4,%5,%6,%7}, {%8,%9}, {%0,%1,%2,%3};"
                 : "+f"(c[0]), "+f"(c[1]), "+f"(c[2]), "+f"(c[3])
                 : "r"(a0), "r"(a1), "r"(a2), "r"(a3), "r"(b0), "r"(b1));
}
#define CP_COMMIT() asm volatile("cp.async.commit_group;" ::: "memory")
#define CP_WAIT0()  asm volatile("cp.async.wait_group 0;" ::: "memory")

// ---------------- kernel 0: init ----------------
__global__ void vq_init_kernel(const float* __restrict__ cb) {
    int j = blockIdx.x * blockDim.x + threadIdx.x;
    if (j == 0) { g_loss_sum = 0.0; g_num_ambig = 0; }
    if (j < KC) {
        const float* er = cb + (size_t)j * EDIM;
        float ee = 0.f;
        #pragma unroll
        for (int k = 0; k < EDIM; ++k) {
            float v = er[k];
            ee = __fadd_rn(ee, __fmul_rn(v, v));          // reference-exact order
            g_BnegT[k * KC + j] = __uint_as_float(cvt_tf32(__fmul_rn(-2.f, v)));
        }
        g_ee[j] = ee;
    }
}

// ---------------- kernel 1: tf32 mma.sync screen + fused argmin ----------------
// smem: A[128][68] f32 @0 (34816B) | B[2][64][136] f32 @34816 (2x34816B)
#define SMEM_A_STRIDE 68
#define SMEM_B_OFF    34816
#define SMEM_B_STRIDE 136
#define SMEM_SZ       104448

__device__ __forceinline__ void cp_chunk(char* smdst, int c, int tid) {
    uint32_t d0 = smem_to_u32(smdst);
    #pragma unroll
    for (int it = 0; it < 8; ++it) {
        int i = tid + it * 256;
        int k = i >> 5, j4 = i & 31;
        uint32_t d = d0 + k * (SMEM_B_STRIDE * 4) + j4 * 16;
        const float* s = g_BnegT + k * KC + c * 128 + j4 * 4;
        asm volatile("cp.async.cg.shared.global [%0], [%1], 16;" :: "r"(d), "l"(s));
    }
}

__global__ __launch_bounds__(256, 2) void vq_screen_mma(const float* __restrict__ x, int nrows) {
    extern __shared__ __align__(16) char sm[];
    int tid = threadIdx.x, wid = tid >> 5, lane = tid & 31;
    int g = lane >> 2, tig = lane & 3;
    int m0 = blockIdx.x * 128;

    // ---- stage A tile (tf32-converted, padded stride 68) ----
    const float4* x4 = (const float4*)(x + (size_t)m0 * EDIM);
    #pragma unroll
    for (int it = 0; it < 8; ++it) {
        int i = tid + it * 256;
        int row = i >> 4, c4 = i & 15;
        uint4 u = make_uint4(0u, 0u, 0u, 0u);
        if (m0 + row < nrows) {
            float4 v = x4[i];
            u.x = cvt_tf32(v.x); u.y = cvt_tf32(v.y);
            u.z = cvt_tf32(v.z); u.w = cvt_tf32(v.w);
        }
        *(uint4*)(sm + row * (SMEM_A_STRIDE * 4) + c4 * 16) = u;
    }
    cp_chunk(sm + SMEM_B_OFF, 0, tid);
    CP_COMMIT();
    CP_WAIT0();
    __syncthreads();

    // ---- load A fragments into registers (one m16 tile per warp) ----
    const uint32_t* pa = (const uint32_t*)sm + (wid * 16 + g) * SMEM_A_STRIDE + tig;
    uint32_t A0[8], A1[8], A2[8], A3[8];
    #pragma unroll
    for (int s = 0; s < 8; ++s) {
        A0[s] = pa[s * 8];
        A2[s] = pa[s * 8 + 4];
        A1[s] = pa[8 * SMEM_A_STRIDE + s * 8];
        A3[s] = pa[8 * SMEM_A_STRIDE + s * 8 + 4];
    }

    float m1s[2] = {3.4e38f, 3.4e38f}, m2s[2] = {3.4e38f, 3.4e38f};
    int   i1s[2] = {0, 0};

    #pragma unroll 1
    for (int c = 0; c < 8; ++c) {
        int buf = c & 1;
        if (c + 1 < 8) {
            cp_chunk(sm + SMEM_B_OFF + (buf ^ 1) * 34816, c + 1, tid);
            CP_COMMIT();
        }
        const uint32_t* pb = (const uint32_t*)(sm + SMEM_B_OFF + buf * 34816)
                             + tig * SMEM_B_STRIDE + g;
        int cbase = c * 128;

        #pragma unroll 1
        for (int tp = 0; tp < 8; ++tp) {
            int t0 = tp * 2;
            float c0[4] = {0.f, 0.f, 0.f, 0.f};
            float c1[4] = {0.f, 0.f, 0.f, 0.f};
            #pragma unroll
            for (int s = 0; s < 8; ++s) {
                const uint32_t* pbs = pb + s * (8 * SMEM_B_STRIDE) + t0 * 8;
                uint32_t b00 = pbs[0];
                uint32_t b01 = pbs[4 * SMEM_B_STRIDE];
                uint32_t b10 = pbs[8];
                uint32_t b11 = pbs[4 * SMEM_B_STRIDE + 8];
                mma_tf32(c0, A0[s], A1[s], A2[s], A3[s], b00, b01);
                mma_tf32(c1, A0[s], A1[s], A2[s], A3[s], b10, b11);
            }
            int jb0 = cbase + t0 * 8 + 2 * tig;
            int jb1 = jb0 + 8;
            // slot 0 = row g, slot 1 = row g+8; ascending j, strict < => first index wins
            #pragma unroll
            for (int slot = 0; slot < 2; ++slot) {
                float v0 = c0[slot * 2], v1 = c0[slot * 2 + 1];
                float w0 = c1[slot * 2], w1 = c1[slot * 2 + 1];
                float m1 = m1s[slot], m2 = m2s[slot]; int i1 = i1s[slot];
                if (v0 < m1) { m2 = m1; m1 = v0; i1 = jb0; }     else if (v0 < m2) m2 = v0;
                if (v1 < m1) { m2 = m1; m1 = v1; i1 = jb0 + 1; } else if (v1 < m2) m2 = v1;
                if (w0 < m1) { m2 = m1; m1 = w0; i1 = jb1; }     else if (w0 < m2) m2 = w0;
                if (w1 < m1) { m2 = m1; m1 = w1; i1 = jb1 + 1; } else if (w1 < m2) m2 = w1;
                m1s[slot] = m1; m2s[slot] = m2; i1s[slot] = i1;
            }
        }
        if (c + 1 < 8) CP_WAIT0();
        __syncthreads();
    }

    // ---- merge across the 4 lanes of each row-quad (lexicographic (val, idx)) ----
    #pragma unroll
    for (int slot = 0; slot < 2; ++slot) {
        float a1 = m1s[slot], a2 = m2s[slot]; int ai = i1s[slot];
        #pragma unroll
        for (int off = 1; off <= 2; off <<= 1) {
            float o1 = __shfl_xor_sync(0xffffffffu, a1, off);
            int   oi = __shfl_xor_sync(0xffffffffu, ai, off);
            float o2 = __shfl_xor_sync(0xffffffffu, a2, off);
            if (o1 < a1 || (o1 == a1 && oi < ai)) {
                a2 = fminf(o2, a1); a1 = o1; ai = oi;
            } else {
                a2 = fminf(a2, o1);
            }
        }
        if (tig == 0) {
            int row = m0 + wid * 16 + g + slot * 8;
            if (row < nrows) {
                g_codes[row] = ai;
                if (a2 - a1 < MARGIN) {
                    int s = atomicAdd(&g_num_ambig, 1);
                    g_ambig_rows[s] = row;
                    g_amb_key[s] = ~0ull;
                }
            }
        }
    }
}

// ---------------- kernel 2: exact reference-numerics rescore (tiled, segmented) ----------------
__global__ __launch_bounds__(256) void vq_rescore_seg(const float* __restrict__ x,
                                                      const float* __restrict__ cb) {
    __shared__ float s_e[128 * EDIM];
    int na = g_num_ambig;
    int nwork = ((na + 255) >> 8) * 8;
    #pragma unroll 1
    for (int w = blockIdx.x; w < nwork; w += gridDim.x) {
        int seg = w & 7, base = (w >> 3) << 8;
        __syncthreads();
        const float4* g4 = (const float4*)(cb + (size_t)seg * 128 * EDIM);
        for (int i = threadIdx.x; i < 2048; i += 256) ((float4*)s_e)[i] = g4[i];
        __syncthreads();
        int s = base + threadIdx.x;
        if (s < na) {
            int row = g_ambig_rows[s];
            const float* xr = x + (size_t)row * EDIM;
            float xv[EDIM];
            #pragma unroll
            for (int k = 0; k < EDIM; ++k) xv[k] = xr[k];
            float xx = 0.f;                                  // reference-exact
            #pragma unroll
            for (int k = 0; k < EDIM; ++k) xx = __fadd_rn(xx, __fmul_rn(xv[k], xv[k]));
            float bd = 3.4e38f; int bi = 0x7fffffff;
            #pragma unroll 1
            for (int jj = 0; jj < 128; jj += 2) {            // 2-way ILP on serial chains
                const float* e0 = s_e + jj * EDIM;
                const float* e1 = e0 + EDIM;
                float a0 = 0.f, a1 = 0.f;
                #pragma unroll
                for (int k = 0; k < EDIM; ++k) {
                    a0 = __fmaf_rn(xv[k], e0[k], a0);
                    a1 = __fmaf_rn(xv[k], e1[k], a1);
                }
                int j0 = seg * 128 + jj;
                float d0 = __fadd_rn(__fadd_rn(xx, __fmul_rn(-2.f, a0)), g_ee[j0]);
                float d1 = __fadd_rn(__fadd_rn(xx, __fmul_rn(-2.f, a1)), g_ee[j0 + 1]);
                if (d0 < bd) { bd = d0; bi = j0; }
                if (d1 < bd) { bd = d1; bi = j0 + 1; }
            }
            unsigned long long key =
                ((unsigned long long)__float_as_uint(bd) << 32) | (unsigned)bi;
            atomicMin(&g_amb_key[s], key);                   // d>0: bit order == numeric order
        }
    }
}

__global__ void vq_rescore_fin() {
    int na = g_num_ambig;
    for (int s = blockIdx.x * blockDim.x + threadIdx.x; s < na; s += gridDim.x * blockDim.x)
        g_codes[g_ambig_rows[s]] = (int)(unsigned)(g_amb_key[s] & 0xffffffffull);
}

// ---------------- kernel 3: straight_through + loss (4 independent chains/thread) ----------------
__global__ __launch_bounds__(256) void vq_st_loss_kernel(
    const float* __restrict__ x, const float* __restrict__ cb,
    float* __restrict__ out, int nrows)
{
    int q = nrows * 4;                       // quarter of the float4 count
    int idx = blockIdx.x * 256 + threadIdx.x;
    double ls = 0.0;
    if (idx < q) {
        int    i4[4]; int code[4];
        float4 xv[4], qv[4];
        #pragma unroll
        for (int t = 0; t < 4; ++t) { i4[t] = idx + t * q; code[t] = g_codes[i4[t] >> 4]; }
        #pragma unroll
        for (int t = 0; t < 4; ++t) {
            xv[t] = ((const float4*)x)[i4[t]];
            qv[t] = ((const float4*)cb)[(size_t)code[t] * 16 + (i4[t] & 15)];
        }
        #pragma unroll
        for (int t = 0; t < 4; ++t) {
            float4 st;
            st.x = __fadd_rn(xv[t].x, __fsub_rn(qv[t].x, xv[t].x));
            st.y = __fadd_rn(xv[t].y, __fsub_rn(qv[t].y, xv[t].y));
            st.z = __fadd_rn(xv[t].z, __fsub_rn(qv[t].z, xv[t].z));
            st.w = __fadd_rn(xv[t].w, __fsub_rn(qv[t].w, xv[t].w));
            ((float4*)out)[i4[t]] = st;
            float dx = __fsub_rn(xv[t].x, qv[t].x), dy = __fsub_rn(xv[t].y, qv[t].y);
            float dz = __fsub_rn(xv[t].z, qv[t].z), dw = __fsub_rn(xv[t].w, qv[t].w);
            ls += (double)__fmul_rn(dx, dx) + (double)__fmul_rn(dy, dy)
                + (double)__fmul_rn(dz, dz) + (double)__fmul_rn(dw, dw);
        }
    }
    #pragma unroll
    for (int off = 16; off; off >>= 1)
        ls += __shfl_down_sync(0xffffffffu, ls, off);
    if ((threadIdx.x & 31) == 0) atomicAdd(&g_loss_sum, ls);
}

// ---------------- kernel 4: codes (as float) + loss scalar ----------------
__global__ void vq_codes_loss_kernel(float* __restrict__ out, int nrows, long long out_size)
{
    long long r    = (long long)blockIdx.x * blockDim.x + threadIdx.x;
    long long coff = (long long)nrows * EDIM;
    if (r < nrows && coff + r < out_size) out[coff + r] = (float)g_codes[r];
    if (r == 0 && coff + nrows < out_size) {
        double mean = g_loss_sum / (double)((long long)nrows * EDIM);
        float  mf   = (float)mean;
        out[coff + nrows] = __fadd_rn(mf, __fmul_rn(0.25f, mf));
    }
}

// ---------------- launch ----------------
extern "C" void kernel_launch(void* const* d_in, const int* in_sizes, int n_in,
                              void* d_out, int out_size)
{
    const float* x  = (const float*)d_in[0];
    const float* cb = (const float*)d_in[1];
    int nx = in_sizes[0], nc = in_sizes[1];
    if (nx < nc) {
        const float* t = x; x = cb; cb = t;
        int ti = nx; nx = nc; nc = ti;
    }
    int nrows = nx / EDIM;
    float* out = (float*)d_out;

    static int s_attr_done = 0;
    if (!s_attr_done) {
        cudaFuncSetAttribute(vq_screen_mma, cudaFuncAttributeMaxDynamicSharedMemorySize, SMEM_SZ);
        s_attr_done = 1;
    }

    vq_init_kernel<<<4, 256>>>(cb);
    vq_screen_mma<<<(nrows + 127) / 128, 256, SMEM_SZ>>>(x, nrows);
    vq_rescore_seg<<<296, 256>>>(x, cb);
    vq_rescore_fin<<<64, 256>>>();
    int q = nrows * 4;
    vq_st_loss_kernel<<<(q + 255) / 256, 256>>>(x, cb, out, nrows);
    vq_codes_loss_kernel<<<(nrows + 255) / 256, 256>>>(out, nrows, (long long)out_size);
}